// round 16
// baseline (speedup 1.0000x reference)
#include <cuda_runtime.h>

#define IN_C 64
#define OUT_C 16
#define EA_D 8
#define HNB 128   // nodes per h-block (128 threads: 32 node-groups x 4 channel-quads)
#define XPAD 68   // x-stage row stride (272B: 16B-aligned)
#define ELOOP 4   // sequential edges per thread-quad in edge_kernel

// scratch: h = x @ lin_w + lin_b  [N, 16]
__device__ __align__(16) float g_h[100000 * OUT_C];
// abs-form representation of the attn MLP scalar function:
//   f(t) = C1 + C2*t + sum_j d[j]*|t - r[j]|
__device__ __align__(16) float g_r[16];
__device__ __align__(16) float g_d[16];
__device__ float g_C[2];

// ---------------------------------------------------------------------------
// h = x @ lin_w + lin_b. x staged coalesced into padded smem; thread owns
// 4 channels x 4 nodes so each weight LDS.128 feeds 16 FMA. Also zeroes out[]
// and (block 0, thread 0) builds the abs-form constants for the attn MLP.
// ---------------------------------------------------------------------------
__global__ __launch_bounds__(128) void h_kernel(
        const float* __restrict__ x, const float* __restrict__ lw,
        const float* __restrict__ lb, float* __restrict__ out,
        const float* __restrict__ w1, const float* __restrict__ b1,
        const float* __restrict__ w2, const float* __restrict__ b2, int n) {
    __shared__ __align__(16) float ws[IN_C * OUT_C];
    __shared__ float bs[OUT_C];
    __shared__ __align__(16) float xs[HNB * XPAD];
    int t = threadIdx.x;
    for (int i = t; i < IN_C * OUT_C; i += 128) ws[i] = lw[i];
    if (t < OUT_C) bs[t] = lb[t];

    // ---- block 0, thread 0: abs-form constants ----
    // relu(v) = (v + |v|)/2  =>  f(t) = C1 + C2*t + sum d_j |t - r_j|
    if (blockIdx.x == 0 && t == 0) {
        float C1 = b2[0], C2 = 0.0f;
#pragma unroll
        for (int j = 0; j < 16; j++) {
            float w1j = w1[j], b1j = b1[j], w2j = w2[j];
            if (w1j == 0.0f) {
                C1 += w2j * fmaxf(b1j, 0.0f);
                g_r[j] = 0.0f;
                g_d[j] = 0.0f;
            } else {
                C1 += 0.5f * w2j * b1j;
                C2 += 0.5f * w2j * w1j;
                g_r[j] = -b1j / w1j;
                g_d[j] = 0.5f * w2j * fabsf(w1j);
            }
        }
        g_C[0] = C1;
        g_C[1] = C2;
    }

    // ---- coalesced stage of x tile (HNB rows x 64 floats) ----
    {
        const float4* xg = (const float4*)x;
        int tile4 = blockIdx.x * HNB * (IN_C / 4);
        int total4 = n * (IN_C / 4);
#pragma unroll
        for (int j = 0; j < HNB * (IN_C / 4) / 128; j++) {
            int i = t + j * 128;
            int g4 = tile4 + i;
            float4 v = (g4 < total4) ? xg[g4] : make_float4(0.f, 0.f, 0.f, 0.f);
            int node = i >> 4, m = i & 15;
            *(float4*)&xs[node * XPAD + m * 4] = v;
        }
    }
    __syncthreads();

    int g = t >> 2;      // 0..31: node group (owns nodes g, g+32, g+64, g+96)
    int c4 = t & 3;      // channel quad: channels [c4*4, c4*4+4)

    float4 bias = *(const float4*)&bs[c4 * 4];
    float acc[4][4];
#pragma unroll
    for (int i = 0; i < 4; i++) {
        acc[i][0] = bias.x; acc[i][1] = bias.y;
        acc[i][2] = bias.z; acc[i][3] = bias.w;
    }

#pragma unroll 4
    for (int k4 = 0; k4 < IN_C / 4; k4++) {
        float4 wv[4];
#pragma unroll
        for (int kk = 0; kk < 4; kk++)
            wv[kk] = *(const float4*)&ws[(k4 * 4 + kk) * OUT_C + c4 * 4];
        float4 xv[4];
#pragma unroll
        for (int i = 0; i < 4; i++)
            xv[i] = *(const float4*)&xs[(g + 32 * i) * XPAD + k4 * 4];
#pragma unroll
        for (int i = 0; i < 4; i++) {
            acc[i][0] = fmaf(xv[i].x, wv[0].x, acc[i][0]);
            acc[i][1] = fmaf(xv[i].x, wv[0].y, acc[i][1]);
            acc[i][2] = fmaf(xv[i].x, wv[0].z, acc[i][2]);
            acc[i][3] = fmaf(xv[i].x, wv[0].w, acc[i][3]);
            acc[i][0] = fmaf(xv[i].y, wv[1].x, acc[i][0]);
            acc[i][1] = fmaf(xv[i].y, wv[1].y, acc[i][1]);
            acc[i][2] = fmaf(xv[i].y, wv[1].z, acc[i][2]);
            acc[i][3] = fmaf(xv[i].y, wv[1].w, acc[i][3]);
            acc[i][0] = fmaf(xv[i].z, wv[2].x, acc[i][0]);
            acc[i][1] = fmaf(xv[i].z, wv[2].y, acc[i][1]);
            acc[i][2] = fmaf(xv[i].z, wv[2].z, acc[i][2]);
            acc[i][3] = fmaf(xv[i].z, wv[2].w, acc[i][3]);
            acc[i][0] = fmaf(xv[i].w, wv[3].x, acc[i][0]);
            acc[i][1] = fmaf(xv[i].w, wv[3].y, acc[i][1]);
            acc[i][2] = fmaf(xv[i].w, wv[3].z, acc[i][2]);
            acc[i][3] = fmaf(xv[i].w, wv[3].w, acc[i][3]);
        }
    }

    int base = blockIdx.x * HNB;
#pragma unroll
    for (int i = 0; i < 4; i++) {
        int node = base + g + 32 * i;
        if (node < n) {
            *(float4*)&g_h[(size_t)node * OUT_C + c4 * 4] =
                make_float4(acc[i][0], acc[i][1], acc[i][2], acc[i][3]);
            *(float4*)&out[(size_t)node * OUT_C + c4 * 4] =
                make_float4(0.f, 0.f, 0.f, 0.f);   // replaces cudaMemsetAsync
        }
    }
}

// ---------------------------------------------------------------------------
// Edge kernel: 4 threads per edge (quad), lane sub owns 4 channels, ELOOP
// edges per quad. Scores computed in CLOSED FORM on the fma pipe:
//   f(t) = C1 + C2*t + sum_j d[j]*|t - r[j]|     (no table, no LDS, no shfl)
// with (r, d) held in registers, amortized over ELOOP edges.
// Softmax without max-subtraction (scores analytically bounded).
// ---------------------------------------------------------------------------
__global__ __launch_bounds__(256) void edge_kernel(
        const int* __restrict__ ei, const float* __restrict__ eattr,
        const float* __restrict__ eaw, const float* __restrict__ eab,
        float* __restrict__ out, int E) {
    __shared__ __align__(16) float sw[EA_D * OUT_C];
    __shared__ __align__(16) float sb[OUT_C];
    int t = threadIdx.x;
    if (t < EA_D * OUT_C) sw[t] = eaw[t];
    if (t < OUT_C) sb[t] = eab[t];

    // abs-form constants into registers (uniform across warp -> broadcast LDG)
    float r[16], d[16];
#pragma unroll
    for (int j4 = 0; j4 < 4; j4++) {
        float4 rv = *(const float4*)&g_r[j4 * 4];
        float4 dv = *(const float4*)&g_d[j4 * 4];
        r[j4 * 4 + 0] = rv.x; r[j4 * 4 + 1] = rv.y;
        r[j4 * 4 + 2] = rv.z; r[j4 * 4 + 3] = rv.w;
        d[j4 * 4 + 0] = dv.x; d[j4 * 4 + 1] = dv.y;
        d[j4 * 4 + 2] = dv.z; d[j4 * 4 + 3] = dv.w;
    }
    float C1 = g_C[0], C2 = g_C[1];
    __syncthreads();

    int sub = t & 3;
    int base_e = blockIdx.x * 64 * ELOOP + (t >> 2);

    for (int it = 0; it < ELOOP; it++) {
        int e = base_e + it * 64;
        bool valid = (e < E);
        int ec = valid ? e : 0;          // keep lanes converged for shfl

        int row = ei[ec] - 1;            // edge_index[0] - 1
        int col = ei[E + ec];            // edge_index[1]

        // all 4 lanes of a quad load the full 8 attrs (same addr -> broadcast)
        const float4* ap = (const float4*)(eattr + (size_t)ec * EA_D);
        float4 a0 = ap[0], a1 = ap[1];
        float av[8] = {a0.x, a0.y, a0.z, a0.w, a1.x, a1.y, a1.z, a1.w};

        // gather: one float4 = this lane's 4 channels of the h row
        float4 hva = *(const float4*)(g_h + (size_t)col * OUT_C + sub * 4);

        // ea GEMV for 4 channels (weights from smem, broadcast LDS)
        float4 b4 = *(const float4*)&sb[sub * 4];
        float acc[4] = {b4.x, b4.y, b4.z, b4.w};
#pragma unroll
        for (int k = 0; k < EA_D; k++) {
            float4 w = *(const float4*)&sw[k * OUT_C + sub * 4];
            acc[0] = fmaf(av[k], w.x, acc[0]);
            acc[1] = fmaf(av[k], w.y, acc[1]);
            acc[2] = fmaf(av[k], w.z, acc[2]);
            acc[3] = fmaf(av[k], w.w, acc[3]);
        }
        float agg[4];
        agg[0] = hva.x * acc[0];
        agg[1] = hva.y * acc[1];
        agg[2] = hva.z * acc[2];
        agg[3] = hva.w * acc[3];

        // scores in closed form: f(t) = C1 + C2*t + sum_j d[j]*|t - r[j]|
        float sc[4];
#pragma unroll
        for (int i = 0; i < 4; i++) sc[i] = fmaf(C2, agg[i], C1);
#pragma unroll
        for (int j = 0; j < 16; j++) {
            float rj = r[j], dj = d[j];
#pragma unroll
            for (int i = 0; i < 4; i++)
                sc[i] = fmaf(dj, fabsf(agg[i] - rj), sc[i]);
        }

        // softmax over 16 channels, no max-subtraction (scores bounded small)
        float sum = 0.0f;
#pragma unroll
        for (int i = 0; i < 4; i++) { sc[i] = __expf(sc[i]); sum += sc[i]; }
        sum += __shfl_xor_sync(0xffffffffu, sum, 1, 4);
        sum += __shfl_xor_sync(0xffffffffu, sum, 2, 4);
        float inv = 1.0f / sum;

        if (valid) {
            float v0 = agg[0] * sc[0] * inv;
            float v1 = agg[1] * sc[1] * inv;
            float v2 = agg[2] * sc[2] * inv;
            float v3 = agg[3] * sc[3] * inv;
            float* op = out + (size_t)row * OUT_C + sub * 4;
            asm volatile("red.global.add.v4.f32 [%0], {%1, %2, %3, %4};"
                         :: "l"(op), "f"(v0), "f"(v1), "f"(v2), "f"(v3)
                         : "memory");
        }
    }
}

// ---------------------------------------------------------------------------
extern "C" void kernel_launch(void* const* d_in, const int* in_sizes, int n_in,
                              void* d_out, int out_size) {
    const float* x     = (const float*)d_in[0];
    const int*   ei    = (const int*)  d_in[1];
    const float* eattr = (const float*)d_in[2];
    const float* lw    = (const float*)d_in[3];
    const float* lb    = (const float*)d_in[4];
    const float* eaw   = (const float*)d_in[5];
    const float* eab   = (const float*)d_in[6];
    const float* aw1   = (const float*)d_in[7];
    const float* ab1   = (const float*)d_in[8];
    const float* aw2   = (const float*)d_in[9];
    const float* ab2   = (const float*)d_in[10];
    float* out = (float*)d_out;

    int n = in_sizes[0] / IN_C;
    int E = in_sizes[2] / EA_D;

    h_kernel<<<(n + HNB - 1) / HNB, 128>>>(x, lw, lb, out, aw1, ab1, aw2, ab2, n);
    int epb = 64 * ELOOP;   // edges per block
    edge_kernel<<<(E + epb - 1) / epb, 256>>>(ei, eattr, eaw, eab, out, E);
}

// round 17
// speedup vs baseline: 1.0652x; 1.0652x over previous
#include <cuda_runtime.h>

#define IN_C 64
#define OUT_C 16
#define EA_D 8
#define HNB 128   // nodes per h-block (128 threads: 32 node-groups x 4 channel-quads)
#define XPAD 68   // x-stage row stride (272B: 16B-aligned)

// scratch: h = x @ lin_w + lin_b  [N, 16]
__device__ __align__(16) float g_h[100000 * OUT_C];
// piecewise-linear representation of the attn MLP scalar function
__device__ float g_bp[16];       // sorted breakpoints
__device__ float g_ABf[34];      // 17 (A,B) pairs flattened: f(t)=A*t+B

// ---------------------------------------------------------------------------
// h = x @ lin_w + lin_b. x staged coalesced into padded smem; thread owns
// 4 channels x 4 nodes so each weight LDS.128 feeds 16 FMA. Also zeroes out[]
// and (block 0) builds the pwl tables.
// ---------------------------------------------------------------------------
__global__ __launch_bounds__(128) void h_kernel(
        const float* __restrict__ x, const float* __restrict__ lw,
        const float* __restrict__ lb, float* __restrict__ out,
        const float* __restrict__ w1, const float* __restrict__ b1,
        const float* __restrict__ w2, const float* __restrict__ b2, int n) {
    __shared__ __align__(16) float ws[IN_C * OUT_C];
    __shared__ float bs[OUT_C];
    __shared__ __align__(16) float xs[HNB * XPAD];
    __shared__ float raw[16];
    __shared__ float srt[16];
    int t = threadIdx.x;
    for (int i = t; i < IN_C * OUT_C; i += 128) ws[i] = lw[i];
    if (t < OUT_C) bs[t] = lb[t];

    // ---- block 0: build pwl tables for f(t)=sum relu(t*w1+b1)*w2 + b2 ----
    if (blockIdx.x == 0 && t < 16) {
        float w = w1[t];
        float v;
        if (w == 0.0f) v = 1e30f;
        else {
            v = -b1[t] / w;
            v = fminf(fmaxf(v, -1e30f), 1e30f);
            if (!(v == v)) v = 1e30f;
        }
        raw[t] = v;
    }
    __syncthreads();
    if (blockIdx.x == 0 && t < 16) {
        float v = raw[t];
        int rank = 0;
#pragma unroll
        for (int k = 0; k < 16; k++) {
            float u = raw[k];
            rank += (u < v) || (u == v && k < t);
        }
        srt[rank] = v;
    }
    __syncthreads();
    if (blockIdx.x == 0 && t <= 16) {
        if (t < 16) g_bp[t] = srt[t];
        float tp;
        if (t == 0)       tp = srt[0] - 1.0f;
        else if (t == 16) tp = srt[15] + 1.0f;
        else              tp = 0.5f * srt[t - 1] + 0.5f * srt[t];
        float A = 0.0f, B = b2[0];
#pragma unroll
        for (int j = 0; j < 16; j++) {
            float wj = w1[j], bj = b1[j];
            float v = tp * wj + bj;
            if (v > 0.0f) { A += wj * w2[j]; B += bj * w2[j]; }
        }
        g_ABf[2 * t] = A;
        g_ABf[2 * t + 1] = B;
    }

    // ---- coalesced stage of x tile (HNB rows x 64 floats) ----
    {
        const float4* xg = (const float4*)x;
        int tile4 = blockIdx.x * HNB * (IN_C / 4);
        int total4 = n * (IN_C / 4);
#pragma unroll
        for (int j = 0; j < HNB * (IN_C / 4) / 128; j++) {
            int i = t + j * 128;
            int g4 = tile4 + i;
            float4 v = (g4 < total4) ? xg[g4] : make_float4(0.f, 0.f, 0.f, 0.f);
            int node = i >> 4, m = i & 15;
            *(float4*)&xs[node * XPAD + m * 4] = v;
        }
    }
    __syncthreads();

    int g = t >> 2;      // 0..31: node group (owns nodes g, g+32, g+64, g+96)
    int c4 = t & 3;      // channel quad: channels [c4*4, c4*4+4)

    float4 bias = *(const float4*)&bs[c4 * 4];
    float acc[4][4];
#pragma unroll
    for (int i = 0; i < 4; i++) {
        acc[i][0] = bias.x; acc[i][1] = bias.y;
        acc[i][2] = bias.z; acc[i][3] = bias.w;
    }

#pragma unroll 4
    for (int k4 = 0; k4 < IN_C / 4; k4++) {
        float4 wv[4];
#pragma unroll
        for (int kk = 0; kk < 4; kk++)
            wv[kk] = *(const float4*)&ws[(k4 * 4 + kk) * OUT_C + c4 * 4];
        float4 xv[4];
#pragma unroll
        for (int i = 0; i < 4; i++)
            xv[i] = *(const float4*)&xs[(g + 32 * i) * XPAD + k4 * 4];
#pragma unroll
        for (int i = 0; i < 4; i++) {
            acc[i][0] = fmaf(xv[i].x, wv[0].x, acc[i][0]);
            acc[i][1] = fmaf(xv[i].x, wv[0].y, acc[i][1]);
            acc[i][2] = fmaf(xv[i].x, wv[0].z, acc[i][2]);
            acc[i][3] = fmaf(xv[i].x, wv[0].w, acc[i][3]);
            acc[i][0] = fmaf(xv[i].y, wv[1].x, acc[i][0]);
            acc[i][1] = fmaf(xv[i].y, wv[1].y, acc[i][1]);
            acc[i][2] = fmaf(xv[i].y, wv[1].z, acc[i][2]);
            acc[i][3] = fmaf(xv[i].y, wv[1].w, acc[i][3]);
            acc[i][0] = fmaf(xv[i].z, wv[2].x, acc[i][0]);
            acc[i][1] = fmaf(xv[i].z, wv[2].y, acc[i][1]);
            acc[i][2] = fmaf(xv[i].z, wv[2].z, acc[i][2]);
            acc[i][3] = fmaf(xv[i].z, wv[2].w, acc[i][3]);
            acc[i][0] = fmaf(xv[i].w, wv[3].x, acc[i][0]);
            acc[i][1] = fmaf(xv[i].w, wv[3].y, acc[i][1]);
            acc[i][2] = fmaf(xv[i].w, wv[3].z, acc[i][2]);
            acc[i][3] = fmaf(xv[i].w, wv[3].w, acc[i][3]);
        }
    }

    int base = blockIdx.x * HNB;
#pragma unroll
    for (int i = 0; i < 4; i++) {
        int node = base + g + 32 * i;
        if (node < n) {
            *(float4*)&g_h[(size_t)node * OUT_C + c4 * 4] =
                make_float4(acc[i][0], acc[i][1], acc[i][2], acc[i][3]);
            *(float4*)&out[(size_t)node * OUT_C + c4 * 4] =
                make_float4(0.f, 0.f, 0.f, 0.f);   // replaces cudaMemsetAsync
        }
    }
}

// ---------------------------------------------------------------------------
// Edge kernel: 4 threads per edge (quad), lane sub owns 4 channels.
// pwl interval found by REGISTER count over the 8 odd breakpoints (alu pipe,
// no MIO), then a single shfl resolves the even bit and 2 shfl fetch (A,B):
// 3 shfl/channel instead of 5. Softmax without max-subtraction.
// ---------------------------------------------------------------------------
__global__ __launch_bounds__(256, 6) void edge_kernel(
        const int* __restrict__ ei, const float* __restrict__ eattr,
        const float* __restrict__ eaw, const float* __restrict__ eab,
        float* __restrict__ out, int E) {
    __shared__ __align__(16) float sw[EA_D * OUT_C];
    __shared__ __align__(16) float sb[OUT_C];
    __shared__ float sAB16[2];
    int t = threadIdx.x;
    if (t < EA_D * OUT_C) sw[t] = eaw[t];
    if (t < OUT_C) sb[t] = eab[t];
    if (t == 0) { sAB16[0] = g_ABf[32]; sAB16[1] = g_ABf[33]; }

    // per-lane register slice of the pwl tables (segment of 16 lanes)
    int lane16 = t & 15;
    float bp_l = g_bp[lane16];
    float A_l  = g_ABf[2 * lane16];
    float B_l  = g_ABf[2 * lane16 + 1];
    // the 8 ODD breakpoints, resident in every thread (uniform -> cheap LDG)
    float bpr0 = g_bp[1],  bpr1 = g_bp[3],  bpr2 = g_bp[5],  bpr3 = g_bp[7];
    float bpr4 = g_bp[9],  bpr5 = g_bp[11], bpr6 = g_bp[13], bpr7 = g_bp[15];
    __syncthreads();

    int sub = t & 3;
    int e = blockIdx.x * (blockDim.x >> 2) + (t >> 2);
    bool valid = (e < E);
    int ec = valid ? e : 0;            // keep lanes converged for shfl

    int row = ei[ec] - 1;              // edge_index[0] - 1
    int col = ei[E + ec];              // edge_index[1]

    // all 4 lanes of a quad load the full 8 attrs (same addr -> broadcast)
    const float4* ap = (const float4*)(eattr + (size_t)ec * EA_D);
    float4 a0 = ap[0], a1 = ap[1];
    float av[8] = {a0.x, a0.y, a0.z, a0.w, a1.x, a1.y, a1.z, a1.w};

    // gather: one float4 = this lane's 4 channels of the h row
    float4 hva = *(const float4*)(g_h + (size_t)col * OUT_C + sub * 4);

    // ea GEMV for 4 channels (weights from smem, broadcast LDS)
    float4 b4 = *(const float4*)&sb[sub * 4];
    float acc[4] = {b4.x, b4.y, b4.z, b4.w};
#pragma unroll
    for (int k = 0; k < EA_D; k++) {
        float4 w = *(const float4*)&sw[k * OUT_C + sub * 4];
        acc[0] = fmaf(av[k], w.x, acc[0]);
        acc[1] = fmaf(av[k], w.y, acc[1]);
        acc[2] = fmaf(av[k], w.z, acc[2]);
        acc[3] = fmaf(av[k], w.w, acc[3]);
    }
    float agg[4];
    agg[0] = hva.x * acc[0];
    agg[1] = hva.y * acc[1];
    agg[2] = hva.z * acc[2];
    agg[3] = hva.w * acc[3];

    // interval index p = #{j in 0..15 : t >= bp[j]}:
    //   q = count over odd breakpoints (registers, alu pipe),
    //   p = 2q + (q<8 && t >= bp[2q])  -- one shfl resolves the even bit.
    float sc[4];
#pragma unroll
    for (int i = 0; i < 4; i++) {
        float tv = agg[i];
        int q = (tv >= bpr0) + (tv >= bpr1) + (tv >= bpr2) + (tv >= bpr3)
              + (tv >= bpr4) + (tv >= bpr5) + (tv >= bpr6) + (tv >= bpr7);
        float v = __shfl_sync(0xffffffffu, bp_l, 2 * q, 16);
        int p = 2 * q + ((q < 8) && (tv >= v) ? 1 : 0);
        int pm = p & 15;
        float Av = __shfl_sync(0xffffffffu, A_l, pm, 16);
        float Bv = __shfl_sync(0xffffffffu, B_l, pm, 16);
        if (p == 16) { Av = sAB16[0]; Bv = sAB16[1]; }
        sc[i] = fmaf(Av, tv, Bv);
    }

    // softmax over 16 channels, no max-subtraction (scores bounded small)
    float sum = 0.0f;
#pragma unroll
    for (int i = 0; i < 4; i++) { sc[i] = __expf(sc[i]); sum += sc[i]; }
    sum += __shfl_xor_sync(0xffffffffu, sum, 1, 4);
    sum += __shfl_xor_sync(0xffffffffu, sum, 2, 4);
    float inv = 1.0f / sum;

    if (valid) {
        float v0 = agg[0] * sc[0] * inv;
        float v1 = agg[1] * sc[1] * inv;
        float v2 = agg[2] * sc[2] * inv;
        float v3 = agg[3] * sc[3] * inv;
        float* op = out + (size_t)row * OUT_C + sub * 4;
        asm volatile("red.global.add.v4.f32 [%0], {%1, %2, %3, %4};"
                     :: "l"(op), "f"(v0), "f"(v1), "f"(v2), "f"(v3)
                     : "memory");
    }
}

// ---------------------------------------------------------------------------
extern "C" void kernel_launch(void* const* d_in, const int* in_sizes, int n_in,
                              void* d_out, int out_size) {
    const float* x     = (const float*)d_in[0];
    const int*   ei    = (const int*)  d_in[1];
    const float* eattr = (const float*)d_in[2];
    const float* lw    = (const float*)d_in[3];
    const float* lb    = (const float*)d_in[4];
    const float* eaw   = (const float*)d_in[5];
    const float* eab   = (const float*)d_in[6];
    const float* aw1   = (const float*)d_in[7];
    const float* ab1   = (const float*)d_in[8];
    const float* aw2   = (const float*)d_in[9];
    const float* ab2   = (const float*)d_in[10];
    float* out = (float*)d_out;

    int n = in_sizes[0] / IN_C;
    int E = in_sizes[2] / EA_D;

    h_kernel<<<(n + HNB - 1) / HNB, 128>>>(x, lw, lb, out, aw1, ab1, aw2, ab2, n);
    // 256 threads = 64 edges per block
    edge_kernel<<<(E + 63) / 64, 256>>>(ei, eattr, eaw, eab, out, E);
}